// round 1
// baseline (speedup 1.0000x reference)
#include <cuda_runtime.h>
#include <math.h>

// Problem constants (from reference): B=8, D=1024, N=2048
#define BATCH 8
#define DMODEL 1024
#define SEQ 2048

// Scratch in device globals (no allocations allowed).
__device__ float g_Q[(size_t)BATCH * DMODEL * SEQ];   // 64 MB
__device__ float g_K[(size_t)BATCH * DMODEL * SEQ];   // 64 MB
__device__ float g_V[(size_t)BATCH * DMODEL * SEQ];   // 64 MB
__device__ float g_S[(size_t)BATCH * SEQ * SEQ];      // 128 MB (scores -> attn in place)

// ---------------------------------------------------------------------------
// Tiled SGEMM: C[z] = alpha * op(A[z]) * B[z]
//   TRANS_A = false : A is [M x K] row-major, ld = lda
//   TRANS_A = true  : A is [K x M] row-major, ld = lda  (computes A^T * B)
//   B is [K x N] row-major, ld = ldb. C is [M x N] row-major, ld = ldc.
// Tiles: BM=BN=128, BK=16. 256 threads, each computes 8x8.
// All dims assumed divisible by tile sizes (true for this problem).
// ---------------------------------------------------------------------------
template <bool TRANS_A>
__global__ void __launch_bounds__(256)
sgemm_kernel(const float* __restrict__ Ag, const float* __restrict__ Bg,
             float* __restrict__ Cg,
             int Kdim, int lda, int ldb, int ldc,
             long long sA, long long sB, long long sC, float alpha)
{
    const int tid = threadIdx.x;
    const int m0 = blockIdx.y * 128;
    const int n0 = blockIdx.x * 128;
    const float* A = Ag + (size_t)blockIdx.z * (size_t)sA;
    const float* B = Bg + (size_t)blockIdx.z * (size_t)sB;
    float*       C = Cg + (size_t)blockIdx.z * (size_t)sC;

    __shared__ float As[16][128];
    __shared__ float Bs[16][128];

    float acc[8][8];
#pragma unroll
    for (int i = 0; i < 8; ++i)
#pragma unroll
        for (int j = 0; j < 8; ++j) acc[i][j] = 0.0f;

    const int tx = tid & 15;   // 0..15  -> column group
    const int ty = tid >> 4;   // 0..15  -> row group

    for (int k0 = 0; k0 < Kdim; k0 += 16) {
        // ---- load A tile into As[k][m] ----
        if (TRANS_A) {
            // A is [K x M]: rows k0..k0+15, cols m0..m0+127 (contiguous in m)
#pragma unroll
            for (int l = 0; l < 2; ++l) {
                int idx = tid + l * 256;           // 0..511
                int r = idx >> 5;                  // 0..15  (k within tile)
                int c = (idx & 31) << 2;           // 0,4,...,124 (m within tile)
                float4 v = *(const float4*)(A + (size_t)(k0 + r) * lda + m0 + c);
                *(float4*)&As[r][c] = v;
            }
        } else {
            // A is [M x K]: rows m0..m0+127, cols k0..k0+15 (contiguous in k)
#pragma unroll
            for (int l = 0; l < 2; ++l) {
                int idx = tid + l * 256;           // 0..511
                int r = idx >> 2;                  // 0..127 (m within tile)
                int c = (idx & 3) << 2;            // 0,4,8,12 (k within tile)
                float4 v = *(const float4*)(A + (size_t)(m0 + r) * lda + k0 + c);
                As[c + 0][r] = v.x;
                As[c + 1][r] = v.y;
                As[c + 2][r] = v.z;
                As[c + 3][r] = v.w;
            }
        }
        // ---- load B tile into Bs[k][n] ----
#pragma unroll
        for (int l = 0; l < 2; ++l) {
            int idx = tid + l * 256;
            int r = idx >> 5;                      // 0..15 (k)
            int c = (idx & 31) << 2;               // n within tile
            *(float4*)&Bs[r][c] = *(const float4*)(B + (size_t)(k0 + r) * ldb + n0 + c);
        }
        __syncthreads();

#pragma unroll
        for (int kk = 0; kk < 16; ++kk) {
            float4 a0 = *(const float4*)&As[kk][ty * 8];
            float4 a1 = *(const float4*)&As[kk][ty * 8 + 4];
            float4 b0 = *(const float4*)&Bs[kk][tx * 8];
            float4 b1 = *(const float4*)&Bs[kk][tx * 8 + 4];
            float a[8] = {a0.x, a0.y, a0.z, a0.w, a1.x, a1.y, a1.z, a1.w};
            float b[8] = {b0.x, b0.y, b0.z, b0.w, b1.x, b1.y, b1.z, b1.w};
#pragma unroll
            for (int i = 0; i < 8; ++i)
#pragma unroll
                for (int j = 0; j < 8; ++j)
                    acc[i][j] = fmaf(a[i], b[j], acc[i][j]);
        }
        __syncthreads();
    }

#pragma unroll
    for (int i = 0; i < 8; ++i) {
        float* cp = C + (size_t)(m0 + ty * 8 + i) * ldc + n0 + tx * 8;
        float4 o0 = make_float4(acc[i][0] * alpha, acc[i][1] * alpha,
                                acc[i][2] * alpha, acc[i][3] * alpha);
        float4 o1 = make_float4(acc[i][4] * alpha, acc[i][5] * alpha,
                                acc[i][6] * alpha, acc[i][7] * alpha);
        *(float4*)cp       = o0;
        *(float4*)(cp + 4) = o1;
    }
}

// ---------------------------------------------------------------------------
// Row softmax over rows of length SEQ (=2048). One block of 256 threads/row;
// each thread owns 8 elements kept in registers across the three passes.
// ---------------------------------------------------------------------------
__global__ void __launch_bounds__(256)
softmax_kernel(float* __restrict__ S)
{
    float* p = S + (size_t)blockIdx.x * SEQ;
    const int tid = threadIdx.x;
    __shared__ float red[8];

    float v[8];
    float m = -1e30f;
#pragma unroll
    for (int i = 0; i < 8; ++i) {
        v[i] = p[tid + i * 256];
        m = fmaxf(m, v[i]);
    }
    // block max
#pragma unroll
    for (int o = 16; o; o >>= 1) m = fmaxf(m, __shfl_xor_sync(0xffffffffu, m, o));
    if ((tid & 31) == 0) red[tid >> 5] = m;
    __syncthreads();
    if (tid < 32) {
        float t = (tid < 8) ? red[tid] : -1e30f;
#pragma unroll
        for (int o = 4; o; o >>= 1) t = fmaxf(t, __shfl_xor_sync(0xffffffffu, t, o));
        if (tid == 0) red[0] = t;
    }
    __syncthreads();
    m = red[0];
    __syncthreads();

    float s = 0.0f;
#pragma unroll
    for (int i = 0; i < 8; ++i) {
        v[i] = __expf(v[i] - m);
        s += v[i];
    }
#pragma unroll
    for (int o = 16; o; o >>= 1) s += __shfl_xor_sync(0xffffffffu, s, o);
    if ((tid & 31) == 0) red[tid >> 5] = s;
    __syncthreads();
    if (tid < 32) {
        float t = (tid < 8) ? red[tid] : 0.0f;
#pragma unroll
        for (int o = 4; o; o >>= 1) t += __shfl_xor_sync(0xffffffffu, t, o);
        if (tid == 0) red[0] = t;
    }
    __syncthreads();
    float inv = 1.0f / red[0];
#pragma unroll
    for (int i = 0; i < 8; ++i) p[tid + i * 256] = v[i] * inv;
}

// ---------------------------------------------------------------------------
// Launch: Q/K/V projections -> scores (Q^T K / 32) -> softmax -> V @ attn
// ---------------------------------------------------------------------------
extern "C" void kernel_launch(void* const* d_in, const int* in_sizes, int n_in,
                              void* d_out, int out_size)
{
    const float* x  = (const float*)d_in[0];   // [B, D, N]
    const float* Wq = (const float*)d_in[1];   // [D, D]
    const float* Wk = (const float*)d_in[2];
    const float* Wv = (const float*)d_in[3];
    float* out = (float*)d_out;                // [B, D, N]

    float *Qp, *Kp, *Vp, *Sp;
    cudaGetSymbolAddress((void**)&Qp, g_Q);
    cudaGetSymbolAddress((void**)&Kp, g_K);
    cudaGetSymbolAddress((void**)&Vp, g_V);
    cudaGetSymbolAddress((void**)&Sp, g_S);

    const long long DN = (long long)DMODEL * SEQ;
    const long long NN = (long long)SEQ * SEQ;

    // Projections: C[b] = W @ x[b]   (M=D=1024, N=2048, K=D=1024)
    dim3 gp(SEQ / 128, DMODEL / 128, BATCH);
    sgemm_kernel<false><<<gp, 256>>>(Wq, x, Qp, DMODEL, DMODEL, SEQ, SEQ, 0, DN, DN, 1.0f);
    sgemm_kernel<false><<<gp, 256>>>(Wk, x, Kp, DMODEL, DMODEL, SEQ, SEQ, 0, DN, DN, 1.0f);
    sgemm_kernel<false><<<gp, 256>>>(Wv, x, Vp, DMODEL, DMODEL, SEQ, SEQ, 0, DN, DN, 1.0f);

    // Scores: S[b] = Q[b]^T K[b] / sqrt(D)   (M=N=2048, K=1024), A transposed
    dim3 gs(SEQ / 128, SEQ / 128, BATCH);
    sgemm_kernel<true><<<gs, 256>>>(Qp, Kp, Sp, DMODEL, SEQ, SEQ, SEQ, DN, DN, NN,
                                    1.0f / 32.0f);

    // Softmax over last dim of S (rows of length 2048)
    softmax_kernel<<<BATCH * SEQ, 256>>>(Sp);

    // Output: out[b] = V[b] @ attn[b]   (M=1024, N=2048, K=2048)
    dim3 go(SEQ / 128, DMODEL / 128, BATCH);
    sgemm_kernel<false><<<go, 256>>>(Vp, Sp, out, SEQ, SEQ, SEQ, SEQ, DN, NN, DN, 1.0f);
}

// round 2
// speedup vs baseline: 3.0996x; 3.0996x over previous
#include <cuda_runtime.h>
#include <math.h>

// Problem constants: B=8, D=1024, N=2048
#define BATCH 8
#define DMODEL 1024
#define SEQ 2048

// Scratch (no allocations allowed)
__device__ float g_Q[(size_t)BATCH * DMODEL * SEQ];
__device__ float g_K[(size_t)BATCH * DMODEL * SEQ];
__device__ float g_V[(size_t)BATCH * DMODEL * SEQ];
__device__ float g_S[(size_t)BATCH * SEQ * SEQ];

#define BM 128
#define BN 128
#define BK 32
#define APITCH 36    // As[m][k] non-trans: bank = (4*m + k) % 32 -> conflict-free frags
#define ATPITCH 136  // Ast[k][m] trans:    bank = (8*k + m) % 32 -> conflict-free frags
#define BPITCH 136   // Bs[k][n]:           bank = (8*k + n) % 32 -> conflict-free frags
#define NSTAGE 3

__device__ __forceinline__ unsigned f2tf32(float f) {
    unsigned r;
    asm("cvt.rna.tf32.f32 %0, %1;" : "=r"(r) : "f"(f));
    return r;
}

__device__ __forceinline__ void cp_async16(float* smem, const float* gmem) {
    unsigned s = (unsigned)__cvta_generic_to_shared(smem);
    asm volatile("cp.async.ca.shared.global [%0], [%1], 16;\n" :: "r"(s), "l"(gmem));
}
__device__ __forceinline__ void cp_commit() {
    asm volatile("cp.async.commit_group;\n");
}
template <int N>
__device__ __forceinline__ void cp_wait() {
    asm volatile("cp.async.wait_group %0;\n" :: "n"(N));
}

__device__ __forceinline__ void mma_tf32(float& c0, float& c1, float& c2, float& c3,
                                         unsigned a0, unsigned a1, unsigned a2, unsigned a3,
                                         unsigned b0, unsigned b1) {
    asm volatile(
        "mma.sync.aligned.m16n8k8.row.col.f32.tf32.tf32.f32 "
        "{%0,%1,%2,%3}, {%4,%5,%6,%7}, {%8,%9}, {%0,%1,%2,%3};\n"
        : "+f"(c0), "+f"(c1), "+f"(c2), "+f"(c3)
        : "r"(a0), "r"(a1), "r"(a2), "r"(a3), "r"(b0), "r"(b1));
}

// ---------------------------------------------------------------------------
// TF32 GEMM: C[z] = alpha * op(A[z]) * B[z]
//   TRANS_A=false: A [M x K] row-major; TRANS_A=true: A [K x M] (computes A^T B)
//   B [K x N] row-major; C [M x N] row-major.
// 256 threads = 8 warps, warp tile 64x32, m16n8k8 tf32 mma, 3-stage cp.async.
// Dims divisible by tile sizes (holds for this problem).
// ---------------------------------------------------------------------------
template <bool TRANS_A>
__global__ void __launch_bounds__(256)
mm_tf32(const float* __restrict__ Ag, const float* __restrict__ Bg,
        float* __restrict__ Cg,
        int Kdim, int lda, int ldb, int ldc,
        long long sA, long long sB, long long sC, float alpha)
{
    constexpr int ASZ = TRANS_A ? BK * ATPITCH : BM * APITCH;  // floats per A stage
    constexpr int BSZ = BK * BPITCH;

    extern __shared__ float smem[];
    float* Abuf = smem;               // NSTAGE * ASZ
    float* Bbuf = smem + NSTAGE * ASZ;

    const int tid = threadIdx.x;
    const int m0 = blockIdx.y * BM;
    const int n0 = blockIdx.x * BN;
    const float* A = Ag + (size_t)blockIdx.z * (size_t)sA;
    const float* B = Bg + (size_t)blockIdx.z * (size_t)sB;
    float*       C = Cg + (size_t)blockIdx.z * (size_t)sC;

    const int wid  = tid >> 5;
    const int lane = tid & 31;
    const int gid  = lane >> 2;   // 0..7
    const int tig  = lane & 3;    // 0..3
    const int wm = (wid & 1) * 64;   // warp m offset in tile
    const int wn = (wid >> 1) * 32;  // warp n offset in tile

    float acc[4][4][4];
#pragma unroll
    for (int mt = 0; mt < 4; ++mt)
#pragma unroll
        for (int nt = 0; nt < 4; ++nt)
#pragma unroll
            for (int i = 0; i < 4; ++i) acc[mt][nt][i] = 0.0f;

    // per-thread load coordinates (4 float4 for A, 4 for B per stage)
    auto load_tile = [&](int kt, int buf) {
        const int k0 = kt * BK;
        float* As = Abuf + buf * ASZ;
        float* Bs = Bbuf + buf * BSZ;
#pragma unroll
        for (int i = 0; i < 4; ++i) {
            int l = tid + i * 256;  // 0..1023
            if (TRANS_A) {
                int rk = l >> 5;          // 0..31 (k)
                int c4 = l & 31;          // m / 4
                cp_async16(&As[rk * ATPITCH + c4 * 4],
                           A + (size_t)(k0 + rk) * lda + m0 + c4 * 4);
            } else {
                int rm = l >> 3;          // 0..127 (m)
                int c4 = l & 7;           // k / 4
                cp_async16(&As[rm * APITCH + c4 * 4],
                           A + (size_t)(m0 + rm) * lda + k0 + c4 * 4);
            }
        }
#pragma unroll
        for (int i = 0; i < 4; ++i) {
            int l = tid + i * 256;
            int rk = l >> 5;
            int c4 = l & 31;
            cp_async16(&Bs[rk * BPITCH + c4 * 4],
                       B + (size_t)(k0 + rk) * ldb + n0 + c4 * 4);
        }
        cp_commit();
    };

    const int T = Kdim / BK;
    load_tile(0, 0);
    if (T > 1) load_tile(1, 1);

    for (int kt = 0; kt < T; ++kt) {
        if (kt + 2 < T) {
            load_tile(kt + 2, (kt + 2) % NSTAGE);
            cp_wait<2>();
        } else if (kt + 1 < T) {
            cp_wait<1>();
        } else {
            cp_wait<0>();
        }
        __syncthreads();

        const float* As = Abuf + (kt % NSTAGE) * ASZ;
        const float* Bs = Bbuf + (kt % NSTAGE) * BSZ;

#pragma unroll
        for (int kk = 0; kk < 4; ++kk) {
            const int kb = kk * 8;
            // B fragments: 4 n-tiles x 2 regs
            unsigned bf[4][2];
#pragma unroll
            for (int nt = 0; nt < 4; ++nt) {
                int n = wn + nt * 8 + gid;
                bf[nt][0] = f2tf32(Bs[(kb + tig) * BPITCH + n]);
                bf[nt][1] = f2tf32(Bs[(kb + tig + 4) * BPITCH + n]);
            }
#pragma unroll
            for (int mt = 0; mt < 4; ++mt) {
                unsigned a0, a1, a2, a3;
                if (TRANS_A) {
                    int m = wm + mt * 16 + gid;
                    a0 = f2tf32(As[(kb + tig) * ATPITCH + m]);
                    a1 = f2tf32(As[(kb + tig) * ATPITCH + m + 8]);
                    a2 = f2tf32(As[(kb + tig + 4) * ATPITCH + m]);
                    a3 = f2tf32(As[(kb + tig + 4) * ATPITCH + m + 8]);
                } else {
                    int m = wm + mt * 16 + gid;
                    a0 = f2tf32(As[m * APITCH + kb + tig]);
                    a1 = f2tf32(As[(m + 8) * APITCH + kb + tig]);
                    a2 = f2tf32(As[m * APITCH + kb + tig + 4]);
                    a3 = f2tf32(As[(m + 8) * APITCH + kb + tig + 4]);
                }
#pragma unroll
                for (int nt = 0; nt < 4; ++nt)
                    mma_tf32(acc[mt][nt][0], acc[mt][nt][1],
                             acc[mt][nt][2], acc[mt][nt][3],
                             a0, a1, a2, a3, bf[nt][0], bf[nt][1]);
            }
        }
        __syncthreads();
    }

    // Epilogue: c0,c1 at (gid, 2*tig), c2,c3 at (gid+8, 2*tig)
#pragma unroll
    for (int mt = 0; mt < 4; ++mt) {
#pragma unroll
        for (int nt = 0; nt < 4; ++nt) {
            int r = m0 + wm + mt * 16 + gid;
            int c = n0 + wn + nt * 8 + tig * 2;
            float2 v0 = make_float2(acc[mt][nt][0] * alpha, acc[mt][nt][1] * alpha);
            float2 v1 = make_float2(acc[mt][nt][2] * alpha, acc[mt][nt][3] * alpha);
            *(float2*)(C + (size_t)r * ldc + c)       = v0;
            *(float2*)(C + (size_t)(r + 8) * ldc + c) = v1;
        }
    }
}

// ---------------------------------------------------------------------------
// Row softmax over rows of length SEQ (=2048). 256 threads/row, regs-resident.
// ---------------------------------------------------------------------------
__global__ void __launch_bounds__(256)
softmax_kernel(float* __restrict__ S)
{
    float* p = S + (size_t)blockIdx.x * SEQ;
    const int tid = threadIdx.x;
    __shared__ float red[8];

    float v[8];
    float m = -1e30f;
#pragma unroll
    for (int i = 0; i < 8; ++i) {
        v[i] = p[tid + i * 256];
        m = fmaxf(m, v[i]);
    }
#pragma unroll
    for (int o = 16; o; o >>= 1) m = fmaxf(m, __shfl_xor_sync(0xffffffffu, m, o));
    if ((tid & 31) == 0) red[tid >> 5] = m;
    __syncthreads();
    if (tid < 32) {
        float t = (tid < 8) ? red[tid] : -1e30f;
#pragma unroll
        for (int o = 4; o; o >>= 1) t = fmaxf(t, __shfl_xor_sync(0xffffffffu, t, o));
        if (tid == 0) red[0] = t;
    }
    __syncthreads();
    m = red[0];
    __syncthreads();

    float s = 0.0f;
#pragma unroll
    for (int i = 0; i < 8; ++i) {
        v[i] = __expf(v[i] - m);
        s += v[i];
    }
#pragma unroll
    for (int o = 16; o; o >>= 1) s += __shfl_xor_sync(0xffffffffu, s, o);
    if ((tid & 31) == 0) red[tid >> 5] = s;
    __syncthreads();
    if (tid < 32) {
        float t = (tid < 8) ? red[tid] : 0.0f;
#pragma unroll
        for (int o = 4; o; o >>= 1) t += __shfl_xor_sync(0xffffffffu, t, o);
        if (tid == 0) red[0] = t;
    }
    __syncthreads();
    float inv = 1.0f / red[0];
#pragma unroll
    for (int i = 0; i < 8; ++i) p[tid + i * 256] = v[i] * inv;
}

// ---------------------------------------------------------------------------
extern "C" void kernel_launch(void* const* d_in, const int* in_sizes, int n_in,
                              void* d_out, int out_size)
{
    const float* x  = (const float*)d_in[0];   // [B, D, N]
    const float* Wq = (const float*)d_in[1];   // [D, D]
    const float* Wk = (const float*)d_in[2];
    const float* Wv = (const float*)d_in[3];
    float* out = (float*)d_out;                // [B, D, N]

    float *Qp, *Kp, *Vp, *Sp;
    cudaGetSymbolAddress((void**)&Qp, g_Q);
    cudaGetSymbolAddress((void**)&Kp, g_K);
    cudaGetSymbolAddress((void**)&Vp, g_V);
    cudaGetSymbolAddress((void**)&Sp, g_S);

    // dynamic smem sizes
    constexpr int SM_NT = NSTAGE * (BM * APITCH + BK * BPITCH) * 4;   // non-trans
    constexpr int SM_T  = NSTAGE * (BK * ATPITCH + BK * BPITCH) * 4;  // trans
    static bool attr_set = false;
    if (!attr_set) {
        cudaFuncSetAttribute(mm_tf32<false>, cudaFuncAttributeMaxDynamicSharedMemorySize, SM_NT);
        cudaFuncSetAttribute(mm_tf32<true>,  cudaFuncAttributeMaxDynamicSharedMemorySize, SM_T);
        attr_set = true;
    }

    const long long DN = (long long)DMODEL * SEQ;
    const long long NN = (long long)SEQ * SEQ;

    // Projections: C[b] = W @ x[b]   (M=1024, N=2048, K=1024)
    dim3 gp(SEQ / BN, DMODEL / BM, BATCH);
    mm_tf32<false><<<gp, 256, SM_NT>>>(Wq, x, Qp, DMODEL, DMODEL, SEQ, SEQ, 0, DN, DN, 1.0f);
    mm_tf32<false><<<gp, 256, SM_NT>>>(Wk, x, Kp, DMODEL, DMODEL, SEQ, SEQ, 0, DN, DN, 1.0f);
    mm_tf32<false><<<gp, 256, SM_NT>>>(Wv, x, Vp, DMODEL, DMODEL, SEQ, SEQ, 0, DN, DN, 1.0f);

    // Scores: S[b] = Q[b]^T K[b] / 32   (M=N=2048, K=1024)
    dim3 gs(SEQ / BN, SEQ / BM, BATCH);
    mm_tf32<true><<<gs, 256, SM_T>>>(Qp, Kp, Sp, DMODEL, SEQ, SEQ, SEQ, DN, DN, NN,
                                     1.0f / 32.0f);

    // Softmax
    softmax_kernel<<<BATCH * SEQ, 256>>>(Sp);

    // Output: out[b] = V[b] @ attn[b]   (M=1024, N=2048, K=2048)
    dim3 go(SEQ / BN, DMODEL / BM, BATCH);
    mm_tf32<false><<<go, 256, SM_NT>>>(Vp, Sp, out, SEQ, SEQ, SEQ, SEQ, DN, NN, DN, 1.0f);
}